// round 6
// baseline (speedup 1.0000x reference)
#include <cuda_runtime.h>
#include <cuda_fp16.h>
#include <math.h>
#include <stdint.h>

#define T 2048
#define D 2048
#define E 8
#define F 1408
#define N1 (2 * F)   // interleaved gate/up N dimension = 2816

// ---------------- scratch (device globals; no allocation allowed) ----------
__device__ __align__(16) __half g_Wgu[(size_t)E * D * N1];  // [e][k=d][n=2f+s]
__device__ __align__(16) __half g_Wd [(size_t)E * F * D];   // [e][k=f][n=d]
__device__ __align__(16) __half g_Xh [(size_t)T * D];       // fp16 tokens
__device__ __align__(16) __half g_H  [(size_t)E * T * F];   // silu(g)*u fp16
__device__ int   g_cnt[E];
__device__ int   g_tok[E * T];
__device__ float g_wt [E * T];

// ---------------- helpers ---------------------------------------------------
__global__ void zero_cnt_kernel() {
    if (threadIdx.x < E) g_cnt[threadIdx.x] = 0;
}

// fused gate+up convert, column interleave: dst[..][2f]=gate_f, [2f+1]=up_f
__global__ void convert_gu_kernel(const float4* __restrict__ wg,
                                  const float4* __restrict__ wu, int n4) {
    uint4* dst = (uint4*)g_Wgu;
    for (int i = blockIdx.x * blockDim.x + threadIdx.x; i < n4;
         i += gridDim.x * blockDim.x) {
        float4 g = wg[i];
        float4 u = wu[i];
        __half2 h[4];
        h[0] = __floats2half2_rn(g.x, u.x);
        h[1] = __floats2half2_rn(g.y, u.y);
        h[2] = __floats2half2_rn(g.z, u.z);
        h[3] = __floats2half2_rn(g.w, u.w);
        dst[i] = *(uint4*)h;
    }
}

// which: 0 -> g_Xh, 1 -> g_Wd.  (Device-symbol address resolved IN DEVICE
// code — host code must never take the address of a __device__ array.)
__global__ void convert_f16_kernel(const float4* __restrict__ src,
                                   int which, int n4) {
    __half2* dst = (which == 0) ? (__half2*)g_Xh : (__half2*)g_Wd;
    for (int i = blockIdx.x * blockDim.x + threadIdx.x; i < n4;
         i += gridDim.x * blockDim.x) {
        float4 v = src[i];
        dst[2 * i + 0] = __floats2half2_rn(v.x, v.y);
        dst[2 * i + 1] = __floats2half2_rn(v.z, v.w);
    }
}

// ---------------- router: warp per token ------------------------------------
__global__ void router_kernel(const float4* __restrict__ x4,
                              const float* __restrict__ gw) {
    int warp = threadIdx.x >> 5, lane = threadIdx.x & 31;
    int t = blockIdx.x * 8 + warp;
    float acc[E];
#pragma unroll
    for (int e = 0; e < E; e++) acc[e] = 0.f;
    const float4* xr = x4 + (size_t)t * (D / 4);
    for (int i = lane; i < D / 4; i += 32) {
        float4 v = xr[i];
#pragma unroll
        for (int e = 0; e < E; e++) {
            float4 g = ((const float4*)(gw + (size_t)e * D))[i];
            acc[e] += v.x * g.x + v.y * g.y + v.z * g.z + v.w * g.w;
        }
    }
#pragma unroll
    for (int e = 0; e < E; e++)
#pragma unroll
        for (int o = 16; o; o >>= 1)
            acc[e] += __shfl_xor_sync(0xffffffffu, acc[e], o);
    if (lane == 0) {
        float m = -1e30f;
#pragma unroll
        for (int e = 0; e < E; e++) m = fmaxf(m, acc[e]);
        float p[E], sum = 0.f;
#pragma unroll
        for (int e = 0; e < E; e++) { p[e] = expf(acc[e] - m); sum += p[e]; }
        float inv = 1.f / sum;
#pragma unroll
        for (int e = 0; e < E; e++) p[e] *= inv;
        int i1 = 0;
#pragma unroll
        for (int e = 1; e < E; e++) if (p[e] > p[i1]) i1 = e;
        int i2 = -1;
#pragma unroll
        for (int e = 0; e < E; e++)
            if (e != i1 && (i2 < 0 || p[e] > p[i2])) i2 = e;
        int r1 = atomicAdd(&g_cnt[i1], 1);
        g_tok[i1 * T + r1] = t;  g_wt[i1 * T + r1] = p[i1];
        int r2 = atomicAdd(&g_cnt[i2], 1);
        g_tok[i2 * T + r2] = t;  g_wt[i2 * T + r2] = p[i2];
    }
}

// ---------------- PTX primitives --------------------------------------------
__device__ __forceinline__ unsigned smem_u32(const void* p) {
    return (unsigned)__cvta_generic_to_shared(p);
}
__device__ __forceinline__ void cp16(void* dst, const void* src) {
    asm volatile("cp.async.cg.shared.global [%0], [%1], 16;\n"
                 :: "r"(smem_u32(dst)), "l"(src));
}
__device__ __forceinline__ void cp_commit() {
    asm volatile("cp.async.commit_group;\n");
}
template <int N>
__device__ __forceinline__ void cp_wait() {
    asm volatile("cp.async.wait_group %0;\n" :: "n"(N));
}
__device__ __forceinline__ void ldsm_x4(unsigned& r0, unsigned& r1,
                                        unsigned& r2, unsigned& r3,
                                        const void* p) {
    asm volatile("ldmatrix.sync.aligned.m8n8.x4.shared.b16 {%0,%1,%2,%3}, [%4];\n"
                 : "=r"(r0), "=r"(r1), "=r"(r2), "=r"(r3) : "r"(smem_u32(p)));
}
__device__ __forceinline__ void ldsm_x4t(unsigned& r0, unsigned& r1,
                                         unsigned& r2, unsigned& r3,
                                         const void* p) {
    asm volatile("ldmatrix.sync.aligned.m8n8.x4.trans.shared.b16 {%0,%1,%2,%3}, [%4];\n"
                 : "=r"(r0), "=r"(r1), "=r"(r2), "=r"(r3) : "r"(smem_u32(p)));
}
__device__ __forceinline__ void mma16816(float* c, const unsigned* a,
                                         const unsigned* b) {
    asm volatile(
        "mma.sync.aligned.m16n8k16.row.col.f32.f16.f16.f32 "
        "{%0,%1,%2,%3}, {%4,%5,%6,%7}, {%8,%9}, {%0,%1,%2,%3};\n"
        : "+f"(c[0]), "+f"(c[1]), "+f"(c[2]), "+f"(c[3])
        : "r"(a[0]), "r"(a[1]), "r"(a[2]), "r"(a[3]), "r"(b[0]), "r"(b[1]));
}

// ---------------- tiled GEMM config -----------------------------------------
#define BM 128
#define BN 128
#define BK 32
#define APAD 8            // A row stride 40 halfs = 80B
#define BPAD 8            // B row stride 136 halfs = 272B
#define A_STAGE_BYTES (BM * (BK + APAD) * 2)          // 10240
#define B_STAGE_BYTES (BK * (BN + BPAD) * 2)          // 8704
#define STAGE_BYTES   (A_STAGE_BYTES + B_STAGE_BYTES) // 18944
#define ROWP_BYTES    1024                            // 128 x 8B row pointers
#define SMEM_TOTAL    (ROWP_BYTES + 3 * STAGE_BYTES)  // 57856

#define AS(s) ((__half(*)[BK + APAD])(sm + ROWP_BYTES + (s) * STAGE_BYTES))
#define BS(s) ((__half(*)[BN + BPAD])(sm + ROWP_BYTES + (s) * STAGE_BYTES + A_STAGE_BYTES))

// load one BK-chunk: A rows via smem row-pointer table (handles gather),
// B rows contiguous from weight matrix.
__device__ __forceinline__ void load_chunk(char* sm,
                                           const __half* const* rowp,
                                           const __half* Bp, int ldB, int n0,
                                           int kk0, int stage, int tid) {
#pragma unroll
    for (int i = 0; i < 2; i++) {
        int c = tid + i * 256;               // 512 chunks: 128 rows x 4
        int row = c >> 2, col8 = (c & 3) * 8;
        cp16(&AS(stage)[row][col8], rowp[row] + kk0 + col8);
    }
#pragma unroll
    for (int i = 0; i < 2; i++) {
        int c = tid + i * 256;               // 512 chunks: 32 rows x 16
        int row = c >> 4, col8 = (c & 15) * 8;
        cp16(&BS(stage)[row][col8], Bp + (size_t)(kk0 + row) * ldB + n0 + col8);
    }
    cp_commit();
}

// MODE 0: H = silu(Xh[g_tok] @ Wgu_gate) * (Xh[g_tok] @ Wgu_up)
// MODE 1: out += wt * (H @ Wd)
template <int MODE>
__global__ void __launch_bounds__(256) moe_gemm_kernel(float* __restrict__ out) {
    extern __shared__ char sm[];
    const __half** rowp = (const __half**)sm;

    int e = blockIdx.z;
    int cnt = g_cnt[e];
    int m0 = blockIdx.y * BM;
    if (m0 >= cnt) return;
    int n0 = blockIdx.x * BN;

    const __half* Bp;
    int ldB, NK;
    if (MODE == 0) { Bp = g_Wgu + (size_t)e * D * N1; ldB = N1; NK = D / BK; }
    else           { Bp = g_Wd  + (size_t)e * F * D;  ldB = D;  NK = F / BK; }

    int tid = threadIdx.x;
    if (tid < BM) {
        int r = m0 + tid;
        if (MODE == 0) {
            int tok = g_tok[e * T + (r < cnt ? r : cnt - 1)];
            rowp[tid] = g_Xh + (size_t)tok * D;
        } else {
            rowp[tid] = g_H + ((size_t)e * T + r) * F;
        }
    }
    __syncthreads();

    int warp = tid >> 5, lane = tid & 31;
    int wm = (warp >> 2) * 64;
    int wn = (warp & 3) * 32;
    int grp = lane >> 2, tig = lane & 3;

    float acc[4][4][4];
#pragma unroll
    for (int mi = 0; mi < 4; mi++)
#pragma unroll
        for (int ni = 0; ni < 4; ni++)
#pragma unroll
            for (int q = 0; q < 4; q++) acc[mi][ni][q] = 0.f;

    load_chunk(sm, rowp, Bp, ldB, n0, 0,  0, tid);
    load_chunk(sm, rowp, Bp, ldB, n0, BK, 1, tid);

    for (int kt = 0; kt < NK; kt++) {
        int s = kt % 3;
        if (kt + 1 < NK) cp_wait<1>();
        else             cp_wait<0>();
        __syncthreads();
        if (kt + 2 < NK)
            load_chunk(sm, rowp, Bp, ldB, n0, (kt + 2) * BK, (kt + 2) % 3, tid);
#pragma unroll
        for (int ks = 0; ks < BK; ks += 16) {
            unsigned a[4][4], b[4][2];
            int arow = (lane & 15), acol = ks + ((lane >> 4) << 3);
#pragma unroll
            for (int mi = 0; mi < 4; mi++)
                ldsm_x4(a[mi][0], a[mi][1], a[mi][2], a[mi][3],
                        &AS(s)[wm + mi * 16 + arow][acol]);
            int brow = ks + (lane & 15);
#pragma unroll
            for (int nj = 0; nj < 2; nj++) {
                unsigned r0, r1, r2, r3;
                ldsm_x4t(r0, r1, r2, r3,
                         &BS(s)[brow][wn + nj * 16 + ((lane >> 4) << 3)]);
                b[2 * nj][0] = r0; b[2 * nj][1] = r1;
                b[2 * nj + 1][0] = r2; b[2 * nj + 1][1] = r3;
            }
#pragma unroll
            for (int mi = 0; mi < 4; mi++)
#pragma unroll
                for (int ni = 0; ni < 4; ni++)
                    mma16816(acc[mi][ni], a[mi], b[ni]);
        }
    }

    if (MODE == 0) {
        // (c0,c1) = (gate, up) per thread thanks to column interleave
        __half* Hp = g_H + (size_t)e * T * F;
#pragma unroll
        for (int mi = 0; mi < 4; mi++) {
#pragma unroll
            for (int h = 0; h < 2; h++) {
                int grow = m0 + wm + mi * 16 + grp + h * 8;
                if (grow >= cnt) continue;
                __half* hrow = Hp + (size_t)grow * F;
#pragma unroll
                for (int ni = 0; ni < 4; ni++) {
                    int ng = n0 + wn + ni * 8;
                    int f = (ng >> 1) + tig;
                    float g = acc[mi][ni][h * 2 + 0];
                    float u = acc[mi][ni][h * 2 + 1];
                    float hv = (g / (1.f + __expf(-g))) * u;
                    hrow[f] = __float2half_rn(hv);
                }
            }
        }
    } else {
        int base = e * T;
#pragma unroll
        for (int mi = 0; mi < 4; mi++) {
#pragma unroll
            for (int h = 0; h < 2; h++) {
                int grow = m0 + wm + mi * 16 + grp + h * 8;
                if (grow >= cnt) continue;
                int   tokv = g_tok[base + grow];
                float wv   = g_wt [base + grow];
                float* orow = out + (size_t)tokv * D;
#pragma unroll
                for (int ni = 0; ni < 4; ni++) {
                    int col = n0 + wn + ni * 8 + tig * 2;
                    atomicAdd(&orow[col],     acc[mi][ni][h * 2 + 0] * wv);
                    atomicAdd(&orow[col + 1], acc[mi][ni][h * 2 + 1] * wv);
                }
            }
        }
    }
}

// ---------------- launch ----------------------------------------------------
extern "C" void kernel_launch(void* const* d_in, const int* in_sizes, int n_in,
                              void* d_out, int out_size) {
    const float* x  = (const float*)d_in[0];
    const float* gw = (const float*)d_in[1];
    const float* wg = (const float*)d_in[2];
    const float* wu = (const float*)d_in[3];
    const float* wd = (const float*)d_in[4];
    float* out = (float*)d_out;

    cudaMemsetAsync(d_out, 0, (size_t)T * D * sizeof(float), 0);
    zero_cnt_kernel<<<1, 32>>>();

    router_kernel<<<T / 8, 256>>>((const float4*)x, gw);
    convert_f16_kernel<<<2048, 256>>>((const float4*)x, 0, T * D / 4);

    const int n4 = (E * D * F) / 4;  // 5,767,168
    convert_gu_kernel<<<4096, 256>>>((const float4*)wg, (const float4*)wu, n4);
    convert_f16_kernel<<<4096, 256>>>((const float4*)wd, 1, n4);

    cudaFuncSetAttribute(moe_gemm_kernel<0>,
                         cudaFuncAttributeMaxDynamicSharedMemorySize, SMEM_TOTAL);
    cudaFuncSetAttribute(moe_gemm_kernel<1>,
                         cudaFuncAttributeMaxDynamicSharedMemorySize, SMEM_TOTAL);
    moe_gemm_kernel<0><<<dim3(N1 / BN, T / BM, E), 256, SMEM_TOTAL>>>(nullptr);
    moe_gemm_kernel<1><<<dim3(D / BN, T / BM, E), 256, SMEM_TOTAL>>>(out);
}